// round 8
// baseline (speedup 1.0000x reference)
#include <cuda_runtime.h>
#include <cstdint>

typedef unsigned long long u64;

#define NB   8192
#define SS   64
#define NXX  4
#define NSF  5
#define HH   32
#define SPB  4       // streams (batch elements) per block
#define CH   4       // layer-2 time chunk
#define FULLMASK 0xffffffffu

// ---------- packed f32x2 helpers ----------
static __device__ __forceinline__ u64 ffma2(u64 a, u64 b, u64 c) {
    u64 d; asm("fma.rn.f32x2 %0, %1, %2, %3;" : "=l"(d) : "l"(a), "l"(b), "l"(c)); return d;
}
static __device__ __forceinline__ u64 add2(u64 a, u64 b) {
    u64 d; asm("add.rn.f32x2 %0, %1, %2;" : "=l"(d) : "l"(a), "l"(b)); return d;
}
static __device__ __forceinline__ u64 pk2(float lo, float hi) {
    u64 r; asm("mov.b64 %0, {%1, %2};" : "=l"(r) : "f"(lo), "f"(hi)); return r;
}
static __device__ __forceinline__ u64 pklo(float lo) {
    u64 r; asm("mov.b64 %0, {%1, %2};" : "=l"(r) : "f"(lo), "f"(0.0f)); return r;
}
static __device__ __forceinline__ void up2(u64 v, float& lo, float& hi) {
    asm("mov.b64 {%0, %1}, %2;" : "=f"(lo), "=f"(hi) : "l"(v));
}
static __device__ __forceinline__ float hsum2(u64 v) {
    float x, y; up2(v, x, y); return x + y;
}

// ---------- fast activations (MUFU.TANH) ----------
static __device__ __forceinline__ float tanh_ap(float x) {
    float r; asm("tanh.approx.f32 %0, %1;" : "=f"(r) : "f"(x)); return r;
}
static __device__ __forceinline__ float sigm(float x) {
    return fmaf(tanh_ap(0.5f * x), 0.5f, 0.5f);
}

// fill this warp's k-half of a [4H, H] matrix into W[4][8] (pairs)
static __device__ __forceinline__ void fill_half(u64 W[4][8], const float* __restrict__ M,
                                                 int lane, int kbase) {
    #pragma unroll
    for (int g = 0; g < 4; ++g) {
        const float* src = M + (g * HH + lane) * HH + kbase;
        #pragma unroll
        for (int p = 0; p < 4; ++p) {
            ulonglong2 v = *(const ulonglong2*)(src + 4 * p);
            W[g][2 * p]     = v.x;
            W[g][2 * p + 1] = v.y;
        }
    }
}

// ---- shared memory (bytes) ----
// sy   : float[4][64][32]   layer-1 outputs       32768
// exch : u64[4][4][32]      partial-gate exchange  4096
// hb   : float[4][32]       h broadcast             512
#define OFF_SY   0
#define OFF_EXCH 32768
#define OFF_HB   (32768 + 4096)
#define SMEM_BYTES (OFF_HB + 512)

__global__ void __launch_bounds__(64, 6)
lstm_fused8(const float* __restrict__ x_main,
            const float* __restrict__ x_sfc,
            const float* __restrict__ w_sfc1, const float* __restrict__ b_sfc1,
            const float* __restrict__ w_sfc2, const float* __restrict__ b_sfc2,
            const float* __restrict__ w_ih1,  const float* __restrict__ w_hh1,
            const float* __restrict__ b_ih1,  const float* __restrict__ b_hh1,
            const float* __restrict__ w_ih2,  const float* __restrict__ w_hh2,
            const float* __restrict__ b_ih2,  const float* __restrict__ b_hh2,
            const float* __restrict__ w_out,  const float* __restrict__ b_out,
            float* __restrict__ out)
{
    extern __shared__ char smem[];
    float* sy   = (float*)(smem + OFF_SY);
    u64*   exch = (u64*)(smem + OFF_EXCH);
    float* hb   = (float*)(smem + OFF_HB);

    const int lane  = threadIdx.x & 31;
    const int w     = threadIdx.x >> 5;     // warp id = k-half
    const int kbase = 16 * w;
    const int own0  = 2 * w,     own1  = own0 + 1;     // streams this warp finalizes
    const int peer0 = 2 - 2 * w, peer1 = peer0 + 1;    // streams finalized by the other warp
    const int bbase = blockIdx.x * SPB;

    // ---- layer-1 weights (k-half) ----
    u64 W[4][8];
    fill_half(W, w_hh1, lane, kbase);
    u64 wihp[4][2], bias1p[4];
    #pragma unroll
    for (int g = 0; g < 4; ++g) {
        const int row = g * HH + lane;
        ulonglong2 vi = *(const ulonglong2*)(w_ih1 + row * NXX);
        wihp[g][0] = vi.x;
        wihp[g][1] = vi.y;
        bias1p[g] = pklo(b_ih1[row] + b_hh1[row]);
    }

    // ---- initial state (owned streams) ----
    float c0, c1;
    {
        float a10 = b_sfc1[lane], a20 = b_sfc2[lane];
        float a11 = a10, a21 = a20;
        #pragma unroll
        for (int k = 0; k < NSF; ++k) {
            const float w1v = w_sfc1[lane * NSF + k];
            const float w2v = w_sfc2[lane * NSF + k];
            const float s0 = x_sfc[(bbase + own0) * NSF + k];
            const float s1 = x_sfc[(bbase + own1) * NSF + k];
            a10 += s0 * w1v;  a11 += s1 * w1v;
            a20 += s0 * w2v;  a21 += s1 * w2v;
        }
        hb[own0 * 32 + lane] = tanh_ap(a10);
        hb[own1 * 32 + lane] = tanh_ap(a11);
        c0 = tanh_ap(a20);
        c1 = tanh_ap(a21);
    }
    __syncthreads();

    const float* xs0 = x_main + (size_t)(bbase + own0) * (SS * NXX);
    const float* xs1 = x_main + (size_t)(bbase + own1) * (SS * NXX);

    // ================= layer 1: time-reversed scan =================
    ulonglong2 xv0 = *(const ulonglong2*)(xs0 + (SS - 1) * NXX);
    ulonglong2 xv1 = *(const ulonglong2*)(xs1 + (SS - 1) * NXX);

    #pragma unroll 1
    for (int t = 0; t < SS; ++t) {
        const int s  = SS - 1 - t;
        const int sn = (s > 0) ? s - 1 : 0;

        u64 Ao[2][4], Ap[2][4];
        #pragma unroll
        for (int g = 0; g < 4; ++g) {
            Ao[0][g] = ffma2(xv0.y, wihp[g][1], ffma2(xv0.x, wihp[g][0], bias1p[g]));
            Ao[1][g] = ffma2(xv1.y, wihp[g][1], ffma2(xv1.x, wihp[g][0], bias1p[g]));
            Ap[0][g] = 0ull;
            Ap[1][g] = 0ull;
        }
        // prefetch next x
        ulonglong2 xn0 = *(const ulonglong2*)(xs0 + sn * NXX);
        ulonglong2 xn1 = *(const ulonglong2*)(xs1 + sn * NXX);

        const ulonglong2* ho0 = (const ulonglong2*)(hb + own0  * 32 + kbase);
        const ulonglong2* ho1 = (const ulonglong2*)(hb + own1  * 32 + kbase);
        const ulonglong2* hp0 = (const ulonglong2*)(hb + peer0 * 32 + kbase);
        const ulonglong2* hp1 = (const ulonglong2*)(hb + peer1 * 32 + kbase);
        #pragma unroll
        for (int q = 0; q < 4; ++q) {
            const ulonglong2 v0 = ho0[q], v1 = ho1[q], v2 = hp0[q], v3 = hp1[q];
            #pragma unroll
            for (int g = 0; g < 4; ++g) {
                Ao[0][g] = ffma2(v0.x, W[g][2*q], Ao[0][g]); Ao[0][g] = ffma2(v0.y, W[g][2*q+1], Ao[0][g]);
                Ao[1][g] = ffma2(v1.x, W[g][2*q], Ao[1][g]); Ao[1][g] = ffma2(v1.y, W[g][2*q+1], Ao[1][g]);
                Ap[0][g] = ffma2(v2.x, W[g][2*q], Ap[0][g]); Ap[0][g] = ffma2(v2.y, W[g][2*q+1], Ap[0][g]);
                Ap[1][g] = ffma2(v3.x, W[g][2*q], Ap[1][g]); Ap[1][g] = ffma2(v3.y, W[g][2*q+1], Ap[1][g]);
            }
        }
        // ship peer partials
        #pragma unroll
        for (int g = 0; g < 4; ++g) {
            exch[(peer0 * 4 + g) * 32 + lane] = Ap[0][g];
            exch[(peer1 * 4 + g) * 32 + lane] = Ap[1][g];
        }
        __syncthreads();
        // finalize owned streams
        const float gi0 = hsum2(add2(Ao[0][0], exch[(own0 * 4 + 0) * 32 + lane]));
        const float gf0 = hsum2(add2(Ao[0][1], exch[(own0 * 4 + 1) * 32 + lane]));
        const float gg0 = hsum2(add2(Ao[0][2], exch[(own0 * 4 + 2) * 32 + lane]));
        const float go0 = hsum2(add2(Ao[0][3], exch[(own0 * 4 + 3) * 32 + lane]));
        const float gi1 = hsum2(add2(Ao[1][0], exch[(own1 * 4 + 0) * 32 + lane]));
        const float gf1 = hsum2(add2(Ao[1][1], exch[(own1 * 4 + 1) * 32 + lane]));
        const float gg1 = hsum2(add2(Ao[1][2], exch[(own1 * 4 + 2) * 32 + lane]));
        const float go1 = hsum2(add2(Ao[1][3], exch[(own1 * 4 + 3) * 32 + lane]));
        const float iv0 = sigm(gi0), fv0 = sigm(gf0), gv0 = tanh_ap(gg0), ov0 = sigm(go0);
        const float iv1 = sigm(gi1), fv1 = sigm(gf1), gv1 = tanh_ap(gg1), ov1 = sigm(go1);
        c0 = fv0 * c0 + iv0 * gv0;
        c1 = fv1 * c1 + iv1 * gv1;
        const float h0 = ov0 * tanh_ap(c0);
        const float h1 = ov1 * tanh_ap(c1);
        sy[own0 * (SS * HH) + s * HH + lane] = h0;
        sy[own1 * (SS * HH) + s * HH + lane] = h1;
        hb[own0 * 32 + lane] = h0;
        hb[own1 * 32 + lane] = h1;
        __syncthreads();
        xv0 = xn0;
        xv1 = xn1;
    }

    // ================= layer 2: forward scan =================
    float bias2[4];
    #pragma unroll
    for (int g = 0; g < 4; ++g)
        bias2[g] = b_ih2[g * HH + lane] + b_hh2[g * HH + lane];
    const float wo = w_out[lane];
    const float bo = b_out[0];

    c0 = 0.0f; c1 = 0.0f;
    hb[own0 * 32 + lane] = 0.0f;
    hb[own1 * 32 + lane] = 0.0f;
    __syncthreads();

    #pragma unroll 1
    for (int chk = 0; chk < SS / CH; ++chk) {
        const int t0 = chk * CH;

        // ---- phase A: input projection (W = w_ih2 k-half) ----
        fill_half(W, w_ih2, lane, kbase);
        u64 xg[2][CH][2];      // [own stream][tt][(i,f)/(g,o)]
        #pragma unroll
        for (int tt = 0; tt < CH; ++tt) {
            u64 Ao[2][4], Ap[2][4];
            #pragma unroll
            for (int g = 0; g < 4; ++g) {
                Ao[0][g] = 0ull; Ao[1][g] = 0ull;
                Ap[0][g] = 0ull; Ap[1][g] = 0ull;
            }
            const ulonglong2* y0 = (const ulonglong2*)(sy + own0  * (SS*HH) + (t0+tt) * HH + kbase);
            const ulonglong2* y1 = (const ulonglong2*)(sy + own1  * (SS*HH) + (t0+tt) * HH + kbase);
            const ulonglong2* y2 = (const ulonglong2*)(sy + peer0 * (SS*HH) + (t0+tt) * HH + kbase);
            const ulonglong2* y3 = (const ulonglong2*)(sy + peer1 * (SS*HH) + (t0+tt) * HH + kbase);
            #pragma unroll
            for (int q = 0; q < 4; ++q) {
                const ulonglong2 v0 = y0[q], v1 = y1[q], v2 = y2[q], v3 = y3[q];
                #pragma unroll
                for (int g = 0; g < 4; ++g) {
                    Ao[0][g] = ffma2(v0.x, W[g][2*q], Ao[0][g]); Ao[0][g] = ffma2(v0.y, W[g][2*q+1], Ao[0][g]);
                    Ao[1][g] = ffma2(v1.x, W[g][2*q], Ao[1][g]); Ao[1][g] = ffma2(v1.y, W[g][2*q+1], Ao[1][g]);
                    Ap[0][g] = ffma2(v2.x, W[g][2*q], Ap[0][g]); Ap[0][g] = ffma2(v2.y, W[g][2*q+1], Ap[0][g]);
                    Ap[1][g] = ffma2(v3.x, W[g][2*q], Ap[1][g]); Ap[1][g] = ffma2(v3.y, W[g][2*q+1], Ap[1][g]);
                }
            }
            #pragma unroll
            for (int g = 0; g < 4; ++g) {
                exch[(peer0 * 4 + g) * 32 + lane] = Ap[0][g];
                exch[(peer1 * 4 + g) * 32 + lane] = Ap[1][g];
            }
            __syncthreads();
            xg[0][tt][0] = pk2(hsum2(add2(Ao[0][0], exch[(own0*4+0)*32+lane])) + bias2[0],
                               hsum2(add2(Ao[0][1], exch[(own0*4+1)*32+lane])) + bias2[1]);
            xg[0][tt][1] = pk2(hsum2(add2(Ao[0][2], exch[(own0*4+2)*32+lane])) + bias2[2],
                               hsum2(add2(Ao[0][3], exch[(own0*4+3)*32+lane])) + bias2[3]);
            xg[1][tt][0] = pk2(hsum2(add2(Ao[1][0], exch[(own1*4+0)*32+lane])) + bias2[0],
                               hsum2(add2(Ao[1][1], exch[(own1*4+1)*32+lane])) + bias2[1]);
            xg[1][tt][1] = pk2(hsum2(add2(Ao[1][2], exch[(own1*4+2)*32+lane])) + bias2[2],
                               hsum2(add2(Ao[1][3], exch[(own1*4+3)*32+lane])) + bias2[3]);
            __syncthreads();
        }

        // ---- phase B: recurrence (W = w_hh2 k-half) ----
        fill_half(W, w_hh2, lane, kbase);
        #pragma unroll
        for (int tt = 0; tt < CH; ++tt) {
            u64 Ao[2][4], Ap[2][4];
            {
                float e0, e1, e2, e3;
                up2(xg[0][tt][0], e0, e1); up2(xg[0][tt][1], e2, e3);
                Ao[0][0] = pklo(e0); Ao[0][1] = pklo(e1); Ao[0][2] = pklo(e2); Ao[0][3] = pklo(e3);
                up2(xg[1][tt][0], e0, e1); up2(xg[1][tt][1], e2, e3);
                Ao[1][0] = pklo(e0); Ao[1][1] = pklo(e1); Ao[1][2] = pklo(e2); Ao[1][3] = pklo(e3);
            }
            #pragma unroll
            for (int g = 0; g < 4; ++g) { Ap[0][g] = 0ull; Ap[1][g] = 0ull; }

            const ulonglong2* ho0 = (const ulonglong2*)(hb + own0  * 32 + kbase);
            const ulonglong2* ho1 = (const ulonglong2*)(hb + own1  * 32 + kbase);
            const ulonglong2* hp0 = (const ulonglong2*)(hb + peer0 * 32 + kbase);
            const ulonglong2* hp1 = (const ulonglong2*)(hb + peer1 * 32 + kbase);
            #pragma unroll
            for (int q = 0; q < 4; ++q) {
                const ulonglong2 v0 = ho0[q], v1 = ho1[q], v2 = hp0[q], v3 = hp1[q];
                #pragma unroll
                for (int g = 0; g < 4; ++g) {
                    Ao[0][g] = ffma2(v0.x, W[g][2*q], Ao[0][g]); Ao[0][g] = ffma2(v0.y, W[g][2*q+1], Ao[0][g]);
                    Ao[1][g] = ffma2(v1.x, W[g][2*q], Ao[1][g]); Ao[1][g] = ffma2(v1.y, W[g][2*q+1], Ao[1][g]);
                    Ap[0][g] = ffma2(v2.x, W[g][2*q], Ap[0][g]); Ap[0][g] = ffma2(v2.y, W[g][2*q+1], Ap[0][g]);
                    Ap[1][g] = ffma2(v3.x, W[g][2*q], Ap[1][g]); Ap[1][g] = ffma2(v3.y, W[g][2*q+1], Ap[1][g]);
                }
            }
            #pragma unroll
            for (int g = 0; g < 4; ++g) {
                exch[(peer0 * 4 + g) * 32 + lane] = Ap[0][g];
                exch[(peer1 * 4 + g) * 32 + lane] = Ap[1][g];
            }
            __syncthreads();
            const float gi0 = hsum2(add2(Ao[0][0], exch[(own0*4+0)*32+lane]));
            const float gf0 = hsum2(add2(Ao[0][1], exch[(own0*4+1)*32+lane]));
            const float gg0 = hsum2(add2(Ao[0][2], exch[(own0*4+2)*32+lane]));
            const float go0 = hsum2(add2(Ao[0][3], exch[(own0*4+3)*32+lane]));
            const float gi1 = hsum2(add2(Ao[1][0], exch[(own1*4+0)*32+lane]));
            const float gf1 = hsum2(add2(Ao[1][1], exch[(own1*4+1)*32+lane]));
            const float gg1 = hsum2(add2(Ao[1][2], exch[(own1*4+2)*32+lane]));
            const float go1 = hsum2(add2(Ao[1][3], exch[(own1*4+3)*32+lane]));
            const float iv0 = sigm(gi0), fv0 = sigm(gf0), gv0 = tanh_ap(gg0), ov0 = sigm(go0);
            const float iv1 = sigm(gi1), fv1 = sigm(gf1), gv1 = tanh_ap(gg1), ov1 = sigm(go1);
            c0 = fv0 * c0 + iv0 * gv0;
            c1 = fv1 * c1 + iv1 * gv1;
            const float h20 = ov0 * tanh_ap(c0);
            const float h21 = ov1 * tanh_ap(c1);
            hb[own0 * 32 + lane] = h20;
            hb[own1 * 32 + lane] = h21;

            // output head for owned streams
            float p0 = h20 * wo, p1 = h21 * wo;
            #pragma unroll
            for (int off = 16; off; off >>= 1) {
                p0 += __shfl_xor_sync(FULLMASK, p0, off);
                p1 += __shfl_xor_sync(FULLMASK, p1, off);
            }
            if (lane == 0) {
                out[(size_t)(bbase + own0) * SS + t0 + tt] = p0 + bo;
                out[(size_t)(bbase + own1) * SS + t0 + tt] = p1 + bo;
            }
            __syncthreads();
        }
    }
}

extern "C" void kernel_launch(void* const* d_in, const int* in_sizes, int n_in,
                              void* d_out, int out_size)
{
    const float* x_main = (const float*)d_in[0];
    const float* x_sfc  = (const float*)d_in[1];
    const float* w_sfc1 = (const float*)d_in[2];
    const float* b_sfc1 = (const float*)d_in[3];
    const float* w_sfc2 = (const float*)d_in[4];
    const float* b_sfc2 = (const float*)d_in[5];
    const float* w_ih1  = (const float*)d_in[6];
    const float* w_hh1  = (const float*)d_in[7];
    const float* b_ih1  = (const float*)d_in[8];
    const float* b_hh1  = (const float*)d_in[9];
    const float* w_ih2  = (const float*)d_in[10];
    const float* w_hh2  = (const float*)d_in[11];
    const float* b_ih2  = (const float*)d_in[12];
    const float* b_hh2  = (const float*)d_in[13];
    const float* w_out  = (const float*)d_in[14];
    const float* b_out  = (const float*)d_in[15];
    float* out = (float*)d_out;

    const int blocks = NB / SPB;   // 2048
    lstm_fused8<<<blocks, 64, SMEM_BYTES>>>(
        x_main, x_sfc, w_sfc1, b_sfc1, w_sfc2, b_sfc2,
        w_ih1, w_hh1, b_ih1, b_hh1,
        w_ih2, w_hh2, b_ih2, b_hh2,
        w_out, b_out, out);
}

// round 10
// speedup vs baseline: 1.2778x; 1.2778x over previous
#include <cuda_runtime.h>
#include <cstdint>

typedef unsigned long long u64;

#define NB   8192
#define SS   64
#define NXX  4
#define NSF  5
#define HH   32
#define WPB  4          // warps per block
#define SPW  2          // batch streams per warp (layer 1)
#define BPB  (WPB*SPW)  // 8 batch elements per block
#define CH   4          // layer-2 time chunk
#define NCHK (SS/CH)    // 16
#define FULLMASK 0xffffffffu

// ---------- packed f32x2 helpers ----------
static __device__ __forceinline__ u64 ffma2(u64 a, u64 b, u64 c) {
    u64 d; asm("fma.rn.f32x2 %0, %1, %2, %3;" : "=l"(d) : "l"(a), "l"(b), "l"(c)); return d;
}
static __device__ __forceinline__ u64 pk2(float lo, float hi) {
    u64 r; asm("mov.b64 %0, {%1, %2};" : "=l"(r) : "f"(lo), "f"(hi)); return r;
}
static __device__ __forceinline__ u64 pklo(float lo) {
    u64 r; asm("mov.b64 %0, {%1, %2};" : "=l"(r) : "f"(lo), "f"(0.0f)); return r;
}
static __device__ __forceinline__ void up2(u64 v, float& lo, float& hi) {
    asm("mov.b64 {%0, %1}, %2;" : "=f"(lo), "=f"(hi) : "l"(v));
}
static __device__ __forceinline__ float hsum2(u64 v) {
    float x, y; up2(v, x, y); return x + y;
}

// ---------- fast activations (MUFU.TANH) ----------
static __device__ __forceinline__ float tanh_ap(float x) {
    float r; asm("tanh.approx.f32 %0, %1;" : "=f"(r) : "f"(x)); return r;
}
static __device__ __forceinline__ float sigm(float x) {
    return fmaf(tanh_ap(0.5f * x), 0.5f, 0.5f);
}

#define BAR_SYNC(id) asm volatile("bar.sync %0, %1;" :: "r"(id), "r"(64) : "memory")

// fill full [4H,H] weight matrix into WR[64] pairs (from global, one-time)
static __device__ __forceinline__ void fill_WR(u64 WR[64], const float* __restrict__ M, int lane) {
    #pragma unroll
    for (int g = 0; g < 4; ++g) {
        const float* src = M + (g * HH + lane) * HH;
        #pragma unroll
        for (int qq = 0; qq < 8; ++qq) {
            ulonglong2 v = *(const ulonglong2*)(src + qq * 4);
            WR[g * 16 + 2 * qq]     = v.x;
            WR[g * 16 + 2 * qq + 1] = v.y;
        }
    }
}

// ---- shared memory (bytes) ----
// sy   : float[8][64][32]                       layer-1 outputs   65536
// hb   : float[8][2][32]                        h broadcast        2048
// xgb  : u64[2 pair][2 buf][4 s][4 tt][2][32]   xg hand-off       32768
#define OFF_SY   0
#define OFF_HB   65536
#define OFF_XG   (65536 + 2048)
#define SMEM_BYTES (OFF_XG + 32768)
#define XGIDX(pair,b,s,tt,h) ((((((pair)*2+(b))*4+(s))*4+(tt))*2+(h))*32)

__global__ void __launch_bounds__(WPB * 32, 2)
lstm_fused10(const float* __restrict__ x_main,
             const float* __restrict__ x_sfc,
             const float* __restrict__ w_sfc1, const float* __restrict__ b_sfc1,
             const float* __restrict__ w_sfc2, const float* __restrict__ b_sfc2,
             const float* __restrict__ w_ih1,  const float* __restrict__ w_hh1,
             const float* __restrict__ b_ih1,  const float* __restrict__ b_hh1,
             const float* __restrict__ w_ih2,  const float* __restrict__ w_hh2,
             const float* __restrict__ b_ih2,  const float* __restrict__ b_hh2,
             const float* __restrict__ w_out,  const float* __restrict__ b_out,
             float* __restrict__ out)
{
    extern __shared__ char smem[];
    float* sy  = (float*)(smem + OFF_SY);
    float* hb  = (float*)(smem + OFF_HB);
    u64*   xgb = (u64*)(smem + OFF_XG);

    const int tid  = threadIdx.x;
    const int wid  = tid >> 5;
    const int lane = tid & 31;
    const int bbase = blockIdx.x * BPB + wid * SPW;
    const int ls0   = wid * SPW;

    // ================= layer 1 (2 interleaved streams per warp) =================
    u64 WR[64];
    fill_WR(WR, w_hh1, lane);
    u64 wih[4][2], bias1p[4];
    #pragma unroll
    for (int g = 0; g < 4; ++g) {
        const int row = g * HH + lane;
        ulonglong2 vi = *(const ulonglong2*)(w_ih1 + row * NXX);
        wih[g][0] = vi.x;
        wih[g][1] = vi.y;
        bias1p[g] = pklo(b_ih1[row] + b_hh1[row]);
    }

    float* hb0 = hb + (ls0 + 0) * 64;
    float* hb1 = hb + (ls0 + 1) * 64;
    const float* x0 = x_main + (size_t)(bbase + 0) * (SS * NXX);
    const float* x1 = x_main + (size_t)(bbase + 1) * (SS * NXX);
    float* sy0 = sy + (ls0 + 0) * (SS * HH);
    float* sy1 = sy + (ls0 + 1) * (SS * HH);

    float c0s, c1s;
    {
        float a10 = b_sfc1[lane], a20 = b_sfc2[lane];
        float a11 = a10, a21 = a20;
        #pragma unroll
        for (int k = 0; k < NSF; ++k) {
            const float w1v = w_sfc1[lane * NSF + k];
            const float w2v = w_sfc2[lane * NSF + k];
            const float s0 = x_sfc[(bbase + 0) * NSF + k];
            const float s1 = x_sfc[(bbase + 1) * NSF + k];
            a10 += s0 * w1v;  a11 += s1 * w1v;
            a20 += s0 * w2v;  a21 += s1 * w2v;
        }
        hb0[lane] = tanh_ap(a10);
        hb1[lane] = tanh_ap(a11);
        c0s = tanh_ap(a20);
        c1s = tanh_ap(a21);
    }
    __syncwarp();
    int buf = 0;

    #pragma unroll 1
    for (int t = 0; t < SS; ++t) {
        const int s = SS - 1 - t;
        const ulonglong2 xv0 = *(const ulonglong2*)(x0 + s * NXX);
        const ulonglong2 xv1 = *(const ulonglong2*)(x1 + s * NXX);

        u64 A00 = bias1p[0], A01 = bias1p[1], A02 = bias1p[2], A03 = bias1p[3];
        u64 A10 = bias1p[0], A11 = bias1p[1], A12 = bias1p[2], A13 = bias1p[3];

        A00 = ffma2(xv0.x, wih[0][0], A00);  A10 = ffma2(xv1.x, wih[0][0], A10);
        A00 = ffma2(xv0.y, wih[0][1], A00);  A10 = ffma2(xv1.y, wih[0][1], A10);
        A01 = ffma2(xv0.x, wih[1][0], A01);  A11 = ffma2(xv1.x, wih[1][0], A11);
        A01 = ffma2(xv0.y, wih[1][1], A01);  A11 = ffma2(xv1.y, wih[1][1], A11);
        A02 = ffma2(xv0.x, wih[2][0], A02);  A12 = ffma2(xv1.x, wih[2][0], A12);
        A02 = ffma2(xv0.y, wih[2][1], A02);  A12 = ffma2(xv1.y, wih[2][1], A12);
        A03 = ffma2(xv0.x, wih[3][0], A03);  A13 = ffma2(xv1.x, wih[3][0], A13);
        A03 = ffma2(xv0.y, wih[3][1], A03);  A13 = ffma2(xv1.y, wih[3][1], A13);

        const ulonglong2* hp0 = (const ulonglong2*)(hb0 + buf * 32);
        const ulonglong2* hp1 = (const ulonglong2*)(hb1 + buf * 32);
        #pragma unroll
        for (int q = 0; q < 8; ++q) {
            const ulonglong2 hv0 = hp0[q];
            const ulonglong2 hv1 = hp1[q];
            A00 = ffma2(hv0.x, WR[2*q],      A00);  A10 = ffma2(hv1.x, WR[2*q],      A10);
            A00 = ffma2(hv0.y, WR[2*q+1],    A00);  A10 = ffma2(hv1.y, WR[2*q+1],    A10);
            A01 = ffma2(hv0.x, WR[16+2*q],   A01);  A11 = ffma2(hv1.x, WR[16+2*q],   A11);
            A01 = ffma2(hv0.y, WR[16+2*q+1], A01);  A11 = ffma2(hv1.y, WR[16+2*q+1], A11);
            A02 = ffma2(hv0.x, WR[32+2*q],   A02);  A12 = ffma2(hv1.x, WR[32+2*q],   A12);
            A02 = ffma2(hv0.y, WR[32+2*q+1], A02);  A12 = ffma2(hv1.y, WR[32+2*q+1], A12);
            A03 = ffma2(hv0.x, WR[48+2*q],   A03);  A13 = ffma2(hv1.x, WR[48+2*q],   A13);
            A03 = ffma2(hv0.y, WR[48+2*q+1], A03);  A13 = ffma2(hv1.y, WR[48+2*q+1], A13);
        }

        const float iv0 = sigm(hsum2(A00)), fv0 = sigm(hsum2(A01));
        const float gv0 = tanh_ap(hsum2(A02)), ov0 = sigm(hsum2(A03));
        const float iv1 = sigm(hsum2(A10)), fv1 = sigm(hsum2(A11));
        const float gv1 = tanh_ap(hsum2(A12)), ov1 = sigm(hsum2(A13));
        c0s = fv0 * c0s + iv0 * gv0;
        c1s = fv1 * c1s + iv1 * gv1;
        const float h0 = ov0 * tanh_ap(c0s);
        const float h1 = ov1 * tanh_ap(c1s);
        sy0[s * HH + lane] = h0;
        sy1[s * HH + lane] = h1;
        hb0[(buf ^ 1) * 32 + lane] = h0;
        hb1[(buf ^ 1) * 32 + lane] = h1;
        __syncwarp();
        buf ^= 1;
    }

    __syncthreads();   // all y complete

    // ================= layer 2: warp-specialized A (xg producer) / B (recurrence) =================
    const int pairid = wid >> 1;                 // 0 or 1; pair streams = 4*pairid..+3
    const int flav   = (blockIdx.x / 148) & 1;   // mix A/B across resident blocks per SMSP
    const int barid  = pairid + 1;
    const int sbase  = 4 * pairid;               // first local stream of the pair
    const int gbase  = blockIdx.x * BPB + sbase; // first global batch of the pair

    if ((wid & 1) == flav) {
        // ---------------- A-warp: xg = W_ih2 @ y + bias, one chunk ahead ----------------
        fill_WR(WR, w_ih2, lane);
        float bias2[4];
        #pragma unroll
        for (int g = 0; g < 4; ++g)
            bias2[g] = b_ih2[g * HH + lane] + b_hh2[g * HH + lane];

        #pragma unroll 1
        for (int chk = 0; chk < NCHK; ++chk) {
            const int t0 = chk * CH;
            const int bsel = chk & 1;
            #pragma unroll
            for (int si = 0; si < 4; ++si) {
                const float* yb = sy + (sbase + si) * (SS * HH);
                #pragma unroll
                for (int tp = 0; tp < 2; ++tp) {   // two tt rows at a time
                    const int tta = 2 * tp, ttb = 2 * tp + 1;
                    const ulonglong2* ya = (const ulonglong2*)(yb + (t0 + tta) * HH);
                    const ulonglong2* yc = (const ulonglong2*)(yb + (t0 + ttb) * HH);
                    u64 P0 = 0ull, P1 = 0ull, P2 = 0ull, P3 = 0ull;
                    u64 Q0 = 0ull, Q1 = 0ull, Q2 = 0ull, Q3 = 0ull;
                    #pragma unroll
                    for (int q = 0; q < 8; ++q) {
                        const ulonglong2 va = ya[q];
                        const ulonglong2 vc = yc[q];
                        P0 = ffma2(va.x, WR[2*q],      P0);  Q0 = ffma2(vc.x, WR[2*q],      Q0);
                        P0 = ffma2(va.y, WR[2*q+1],    P0);  Q0 = ffma2(vc.y, WR[2*q+1],    Q0);
                        P1 = ffma2(va.x, WR[16+2*q],   P1);  Q1 = ffma2(vc.x, WR[16+2*q],   Q1);
                        P1 = ffma2(va.y, WR[16+2*q+1], P1);  Q1 = ffma2(vc.y, WR[16+2*q+1], Q1);
                        P2 = ffma2(va.x, WR[32+2*q],   P2);  Q2 = ffma2(vc.x, WR[32+2*q],   Q2);
                        P2 = ffma2(va.y, WR[32+2*q+1], P2);  Q2 = ffma2(vc.y, WR[32+2*q+1], Q2);
                        P3 = ffma2(va.x, WR[48+2*q],   P3);  Q3 = ffma2(vc.x, WR[48+2*q],   Q3);
                        P3 = ffma2(va.y, WR[48+2*q+1], P3);  Q3 = ffma2(vc.y, WR[48+2*q+1], Q3);
                    }
                    xgb[XGIDX(pairid, bsel, si, tta, 0) + lane] =
                        pk2(hsum2(P0) + bias2[0], hsum2(P1) + bias2[1]);
                    xgb[XGIDX(pairid, bsel, si, tta, 1) + lane] =
                        pk2(hsum2(P2) + bias2[2], hsum2(P3) + bias2[3]);
                    xgb[XGIDX(pairid, bsel, si, ttb, 0) + lane] =
                        pk2(hsum2(Q0) + bias2[0], hsum2(Q1) + bias2[1]);
                    xgb[XGIDX(pairid, bsel, si, ttb, 1) + lane] =
                        pk2(hsum2(Q2) + bias2[2], hsum2(Q3) + bias2[3]);
                }
            }
            BAR_SYNC(barid);
        }
    } else {
        // ---------------- B-warp: recurrence for the pair's 4 streams ----------------
        fill_WR(WR, w_hh2, lane);
        const float wo = w_out[lane];
        const float bo = b_out[0];
        float cs[4] = {0.f, 0.f, 0.f, 0.f};
        #pragma unroll
        for (int si = 0; si < 4; ++si)
            hb[(sbase + si) * 64 + lane] = 0.0f;   // buf 0
        __syncwarp();
        int b2 = 0;

        #pragma unroll 1
        for (int chk = 0; chk < NCHK; ++chk) {
            const int t0 = chk * CH;
            const int bsel = chk & 1;
            BAR_SYNC(barid);
            #pragma unroll
            for (int tt = 0; tt < CH; ++tt) {
                u64 Acc[4][4];
                #pragma unroll
                for (int si = 0; si < 4; ++si) {
                    float e0, e1, e2, e3;
                    up2(xgb[XGIDX(pairid, bsel, si, tt, 0) + lane], e0, e1);
                    up2(xgb[XGIDX(pairid, bsel, si, tt, 1) + lane], e2, e3);
                    Acc[si][0] = pklo(e0); Acc[si][1] = pklo(e1);
                    Acc[si][2] = pklo(e2); Acc[si][3] = pklo(e3);
                }
                const ulonglong2* hp[4];
                #pragma unroll
                for (int si = 0; si < 4; ++si)
                    hp[si] = (const ulonglong2*)(hb + (sbase + si) * 64 + b2 * 32);
                #pragma unroll
                for (int q = 0; q < 8; ++q) {
                    #pragma unroll
                    for (int si = 0; si < 4; ++si) {
                        const ulonglong2 hv = hp[si][q];
                        Acc[si][0] = ffma2(hv.x, WR[2*q],      Acc[si][0]);
                        Acc[si][0] = ffma2(hv.y, WR[2*q+1],    Acc[si][0]);
                        Acc[si][1] = ffma2(hv.x, WR[16+2*q],   Acc[si][1]);
                        Acc[si][1] = ffma2(hv.y, WR[16+2*q+1], Acc[si][1]);
                        Acc[si][2] = ffma2(hv.x, WR[32+2*q],   Acc[si][2]);
                        Acc[si][2] = ffma2(hv.y, WR[32+2*q+1], Acc[si][2]);
                        Acc[si][3] = ffma2(hv.x, WR[48+2*q],   Acc[si][3]);
                        Acc[si][3] = ffma2(hv.y, WR[48+2*q+1], Acc[si][3]);
                    }
                }
                float hnew[4];
                #pragma unroll
                for (int si = 0; si < 4; ++si) {
                    const float iv = sigm(hsum2(Acc[si][0]));
                    const float fv = sigm(hsum2(Acc[si][1]));
                    const float gv = tanh_ap(hsum2(Acc[si][2]));
                    const float ov = sigm(hsum2(Acc[si][3]));
                    cs[si] = fv * cs[si] + iv * gv;
                    hnew[si] = ov * tanh_ap(cs[si]);
                    hb[(sbase + si) * 64 + (b2 ^ 1) * 32 + lane] = hnew[si];
                }
                __syncwarp();
                b2 ^= 1;

                // output head: 4 interleaved shfl chains
                float p0 = hnew[0] * wo, p1 = hnew[1] * wo;
                float p2 = hnew[2] * wo, p3 = hnew[3] * wo;
                #pragma unroll
                for (int off = 16; off; off >>= 1) {
                    p0 += __shfl_xor_sync(FULLMASK, p0, off);
                    p1 += __shfl_xor_sync(FULLMASK, p1, off);
                    p2 += __shfl_xor_sync(FULLMASK, p2, off);
                    p3 += __shfl_xor_sync(FULLMASK, p3, off);
                }
                if (lane == 0) {
                    out[(size_t)(gbase + 0) * SS + t0 + tt] = p0 + bo;
                    out[(size_t)(gbase + 1) * SS + t0 + tt] = p1 + bo;
                    out[(size_t)(gbase + 2) * SS + t0 + tt] = p2 + bo;
                    out[(size_t)(gbase + 3) * SS + t0 + tt] = p3 + bo;
                }
            }
        }
    }
}

extern "C" void kernel_launch(void* const* d_in, const int* in_sizes, int n_in,
                              void* d_out, int out_size)
{
    const float* x_main = (const float*)d_in[0];
    const float* x_sfc  = (const float*)d_in[1];
    const float* w_sfc1 = (const float*)d_in[2];
    const float* b_sfc1 = (const float*)d_in[3];
    const float* w_sfc2 = (const float*)d_in[4];
    const float* b_sfc2 = (const float*)d_in[5];
    const float* w_ih1  = (const float*)d_in[6];
    const float* w_hh1  = (const float*)d_in[7];
    const float* b_ih1  = (const float*)d_in[8];
    const float* b_hh1  = (const float*)d_in[9];
    const float* w_ih2  = (const float*)d_in[10];
    const float* w_hh2  = (const float*)d_in[11];
    const float* b_ih2  = (const float*)d_in[12];
    const float* b_hh2  = (const float*)d_in[13];
    const float* w_out  = (const float*)d_in[14];
    const float* b_out  = (const float*)d_in[15];
    float* out = (float*)d_out;

    static bool attr_set = false;
    if (!attr_set) {
        cudaFuncSetAttribute(lstm_fused10, cudaFuncAttributeMaxDynamicSharedMemorySize, SMEM_BYTES);
        attr_set = true;
    }

    const int blocks = NB / BPB;   // 1024
    lstm_fused10<<<blocks, WPB * 32, SMEM_BYTES>>>(
        x_main, x_sfc, w_sfc1, b_sfc1, w_sfc2, b_sfc2,
        w_ih1, w_hh1, b_ih1, b_hh1,
        w_ih2, w_hh2, b_ih2, b_hh2,
        w_out, b_out, out);
}

// round 13
// speedup vs baseline: 1.5873x; 1.2422x over previous
#include <cuda_runtime.h>
#include <cstdint>

typedef unsigned long long u64;

#define NB   8192
#define SS   64
#define NXX  4
#define NSF  5
#define HH   32
#define WPB  4          // warps per block
#define SPW  2          // batch streams per warp
#define BPB  (WPB*SPW)  // 8 batch elements per block
#define CH   4          // layer-2 time chunk
#define FULLMASK 0xffffffffu

// ---------- packed f32x2 helpers ----------
static __device__ __forceinline__ u64 ffma2(u64 a, u64 b, u64 c) {
    u64 d; asm("fma.rn.f32x2 %0, %1, %2, %3;" : "=l"(d) : "l"(a), "l"(b), "l"(c)); return d;
}
static __device__ __forceinline__ u64 pk2(float lo, float hi) {
    u64 r; asm("mov.b64 %0, {%1, %2};" : "=l"(r) : "f"(lo), "f"(hi)); return r;
}
static __device__ __forceinline__ u64 pklo(float lo) {
    u64 r; asm("mov.b64 %0, {%1, %2};" : "=l"(r) : "f"(lo), "f"(0.0f)); return r;
}
static __device__ __forceinline__ void up2(u64 v, float& lo, float& hi) {
    asm("mov.b64 {%0, %1}, %2;" : "=f"(lo), "=f"(hi) : "l"(v));
}
static __device__ __forceinline__ float hsum2(u64 v) {
    float x, y; up2(v, x, y); return x + y;
}

// ---------- fast activations (MUFU.TANH) ----------
static __device__ __forceinline__ float tanh_ap(float x) {
    float r; asm("tanh.approx.f32 %0, %1;" : "=f"(r) : "f"(x)); return r;
}
static __device__ __forceinline__ float sigm(float x) {
    return fmaf(tanh_ap(0.5f * x), 0.5f, 0.5f);
}

// ---- shared memory (bytes) ----
// w2t : ulonglong2[2][8][128]  layer-2 weights                       32768
// sy  : float[8][64][32]       layer-1 outputs -> layer-2 h2         65536
// hb  : float[8][2][32]        h broadcast double buffers             2048
// swo : float[32]              w_out staged                            128
#define OFF_W2T  0
#define OFF_SY   32768
#define OFF_HB   (32768 + 65536)
#define OFF_SWO  (OFF_HB + 2048)
#define SMEM_BYTES (OFF_SWO + 128)

__global__ void __launch_bounds__(WPB * 32, 2)
lstm_fused11(const float* __restrict__ x_main,
             const float* __restrict__ x_sfc,
             const float* __restrict__ w_sfc1, const float* __restrict__ b_sfc1,
             const float* __restrict__ w_sfc2, const float* __restrict__ b_sfc2,
             const float* __restrict__ w_ih1,  const float* __restrict__ w_hh1,
             const float* __restrict__ b_ih1,  const float* __restrict__ b_hh1,
             const float* __restrict__ w_ih2,  const float* __restrict__ w_hh2,
             const float* __restrict__ b_ih2,  const float* __restrict__ b_hh2,
             const float* __restrict__ w_out,  const float* __restrict__ b_out,
             float* __restrict__ out)
{
    extern __shared__ char smem[];
    ulonglong2* w2t = (ulonglong2*)(smem + OFF_W2T);   // [(m*8+qq)*128 + row]
    float* sy  = (float*)(smem + OFF_SY);
    float* hb  = (float*)(smem + OFF_HB);
    float* swo = (float*)(smem + OFF_SWO);

    const int tid  = threadIdx.x;
    const int wid  = tid >> 5;
    const int lane = tid & 31;
    const int bbase = blockIdx.x * BPB + wid * SPW;
    const int ls0   = wid * SPW;

    // ---- stage layer-2 weights + w_out into smem ----
    #pragma unroll 4
    for (int i = tid; i < 2 * 8 * 128; i += WPB * 32) {
        const int m   = i >> 10;
        const int qq  = (i >> 7) & 7;
        const int row = i & 127;
        const float* src = (m ? w_hh2 : w_ih2) + row * HH + qq * 4;
        w2t[i] = *(const ulonglong2*)src;
    }
    if (tid < 32) swo[tid] = w_out[tid];
    __syncthreads();

    // ---- layer-1 weights -> registers ----
    u64 WR[64];    // WR[g*16 + 2qq + j]
    #pragma unroll
    for (int g = 0; g < 4; ++g) {
        const int row = g * HH + lane;
        #pragma unroll
        for (int qq = 0; qq < 8; ++qq) {
            ulonglong2 v = *(const ulonglong2*)(w_hh1 + row * HH + qq * 4);
            WR[g * 16 + 2 * qq]     = v.x;
            WR[g * 16 + 2 * qq + 1] = v.y;
        }
    }
    u64 wih[4][2], bias1p[4];
    #pragma unroll
    for (int g = 0; g < 4; ++g) {
        const int row = g * HH + lane;
        ulonglong2 vi = *(const ulonglong2*)(w_ih1 + row * NXX);
        wih[g][0] = vi.x;
        wih[g][1] = vi.y;
        bias1p[g] = pklo(b_ih1[row] + b_hh1[row]);
    }

    float* hb0 = hb + (ls0 + 0) * 64;
    float* hb1 = hb + (ls0 + 1) * 64;
    const float* x0 = x_main + (size_t)(bbase + 0) * (SS * NXX);
    const float* x1 = x_main + (size_t)(bbase + 1) * (SS * NXX);
    float* sy0 = sy + (ls0 + 0) * (SS * HH);
    float* sy1 = sy + (ls0 + 1) * (SS * HH);

    // ---- initial state from surface MLPs ----
    float c0s, c1s;
    {
        float a10 = b_sfc1[lane], a20 = b_sfc2[lane];
        float a11 = a10, a21 = a20;
        #pragma unroll
        for (int k = 0; k < NSF; ++k) {
            const float w1v = w_sfc1[lane * NSF + k];
            const float w2v = w_sfc2[lane * NSF + k];
            const float s0 = x_sfc[(bbase + 0) * NSF + k];
            const float s1 = x_sfc[(bbase + 1) * NSF + k];
            a10 += s0 * w1v;  a11 += s1 * w1v;
            a20 += s0 * w2v;  a21 += s1 * w2v;
        }
        hb0[lane] = tanh_ap(a10);
        hb1[lane] = tanh_ap(a11);
        c0s = tanh_ap(a20);
        c1s = tanh_ap(a21);
    }
    __syncwarp();
    int buf = 0;

    // ================= layer 1: time-reversed scan, interleaved streams =================
    #pragma unroll 1
    for (int t = 0; t < SS; ++t) {
        const int s = SS - 1 - t;
        const ulonglong2 xv0 = *(const ulonglong2*)(x0 + s * NXX);
        const ulonglong2 xv1 = *(const ulonglong2*)(x1 + s * NXX);

        u64 A00 = bias1p[0], A01 = bias1p[1], A02 = bias1p[2], A03 = bias1p[3];
        u64 A10 = bias1p[0], A11 = bias1p[1], A12 = bias1p[2], A13 = bias1p[3];

        A00 = ffma2(xv0.x, wih[0][0], A00);  A10 = ffma2(xv1.x, wih[0][0], A10);
        A00 = ffma2(xv0.y, wih[0][1], A00);  A10 = ffma2(xv1.y, wih[0][1], A10);
        A01 = ffma2(xv0.x, wih[1][0], A01);  A11 = ffma2(xv1.x, wih[1][0], A11);
        A01 = ffma2(xv0.y, wih[1][1], A01);  A11 = ffma2(xv1.y, wih[1][1], A11);
        A02 = ffma2(xv0.x, wih[2][0], A02);  A12 = ffma2(xv1.x, wih[2][0], A12);
        A02 = ffma2(xv0.y, wih[2][1], A02);  A12 = ffma2(xv1.y, wih[2][1], A12);
        A03 = ffma2(xv0.x, wih[3][0], A03);  A13 = ffma2(xv1.x, wih[3][0], A13);
        A03 = ffma2(xv0.y, wih[3][1], A03);  A13 = ffma2(xv1.y, wih[3][1], A13);

        const ulonglong2* hp0 = (const ulonglong2*)(hb0 + buf * 32);
        const ulonglong2* hp1 = (const ulonglong2*)(hb1 + buf * 32);
        #pragma unroll
        for (int q = 0; q < 8; ++q) {
            const ulonglong2 hv0 = hp0[q];
            const ulonglong2 hv1 = hp1[q];
            A00 = ffma2(hv0.x, WR[2*q],      A00);  A10 = ffma2(hv1.x, WR[2*q],      A10);
            A00 = ffma2(hv0.y, WR[2*q+1],    A00);  A10 = ffma2(hv1.y, WR[2*q+1],    A10);
            A01 = ffma2(hv0.x, WR[16+2*q],   A01);  A11 = ffma2(hv1.x, WR[16+2*q],   A11);
            A01 = ffma2(hv0.y, WR[16+2*q+1], A01);  A11 = ffma2(hv1.y, WR[16+2*q+1], A11);
            A02 = ffma2(hv0.x, WR[32+2*q],   A02);  A12 = ffma2(hv1.x, WR[32+2*q],   A12);
            A02 = ffma2(hv0.y, WR[32+2*q+1], A02);  A12 = ffma2(hv1.y, WR[32+2*q+1], A12);
            A03 = ffma2(hv0.x, WR[48+2*q],   A03);  A13 = ffma2(hv1.x, WR[48+2*q],   A13);
            A03 = ffma2(hv0.y, WR[48+2*q+1], A03);  A13 = ffma2(hv1.y, WR[48+2*q+1], A13);
        }

        const float iv0 = sigm(hsum2(A00)), fv0 = sigm(hsum2(A01));
        const float gv0 = tanh_ap(hsum2(A02)), ov0 = sigm(hsum2(A03));
        const float iv1 = sigm(hsum2(A10)), fv1 = sigm(hsum2(A11));
        const float gv1 = tanh_ap(hsum2(A12)), ov1 = sigm(hsum2(A13));
        c0s = fv0 * c0s + iv0 * gv0;
        c1s = fv1 * c1s + iv1 * gv1;
        const float h0 = ov0 * tanh_ap(c0s);
        const float h1 = ov1 * tanh_ap(c1s);
        sy0[s * HH + lane] = h0;
        sy1[s * HH + lane] = h1;
        hb0[(buf ^ 1) * 32 + lane] = h0;
        hb1[(buf ^ 1) * 32 + lane] = h1;
        __syncwarp();
        buf ^= 1;
    }

    // ================= layer 2: forward scan =================
    float bias2[4];
    #pragma unroll
    for (int g = 0; g < 4; ++g)
        bias2[g] = b_ih2[g * HH + lane] + b_hh2[g * HH + lane];

    c0s = 0.0f; c1s = 0.0f;
    hb0[buf * 32 + lane] = 0.0f;
    hb1[buf * 32 + lane] = 0.0f;
    __syncwarp();

    u64 xg0[CH][2], xg1[CH][2];

    #pragma unroll 1
    for (int chk = 0; chk < SS / CH; ++chk) {
        const int t0 = chk * CH;

        // ---- phase A: input projection (w_ih2 in WR) ----
        #pragma unroll
        for (int g = 0; g < 4; ++g)
            #pragma unroll
            for (int qq = 0; qq < 8; ++qq) {
                ulonglong2 v = w2t[qq * 128 + g * 32 + lane];
                WR[g * 16 + 2 * qq]     = v.x;
                WR[g * 16 + 2 * qq + 1] = v.y;
            }
        #pragma unroll
        for (int tt = 0; tt < CH; ++tt) {
            const ulonglong2* yp0 = (const ulonglong2*)(sy0 + (t0 + tt) * HH);
            const ulonglong2* yp1 = (const ulonglong2*)(sy1 + (t0 + tt) * HH);
            u64 A00 = 0ull, A01 = 0ull, A02 = 0ull, A03 = 0ull;
            u64 A10 = 0ull, A11 = 0ull, A12 = 0ull, A13 = 0ull;
            #pragma unroll
            for (int q = 0; q < 8; ++q) {
                const ulonglong2 hv0 = yp0[q];
                const ulonglong2 hv1 = yp1[q];
                A00 = ffma2(hv0.x, WR[2*q],      A00);  A10 = ffma2(hv1.x, WR[2*q],      A10);
                A00 = ffma2(hv0.y, WR[2*q+1],    A00);  A10 = ffma2(hv1.y, WR[2*q+1],    A10);
                A01 = ffma2(hv0.x, WR[16+2*q],   A01);  A11 = ffma2(hv1.x, WR[16+2*q],   A11);
                A01 = ffma2(hv0.y, WR[16+2*q+1], A01);  A11 = ffma2(hv1.y, WR[16+2*q+1], A11);
                A02 = ffma2(hv0.x, WR[32+2*q],   A02);  A12 = ffma2(hv1.x, WR[32+2*q],   A12);
                A02 = ffma2(hv0.y, WR[32+2*q+1], A02);  A12 = ffma2(hv1.y, WR[32+2*q+1], A12);
                A03 = ffma2(hv0.x, WR[48+2*q],   A03);  A13 = ffma2(hv1.x, WR[48+2*q],   A13);
                A03 = ffma2(hv0.y, WR[48+2*q+1], A03);  A13 = ffma2(hv1.y, WR[48+2*q+1], A13);
            }
            xg0[tt][0] = pk2(hsum2(A00) + bias2[0], hsum2(A01) + bias2[1]);
            xg0[tt][1] = pk2(hsum2(A02) + bias2[2], hsum2(A03) + bias2[3]);
            xg1[tt][0] = pk2(hsum2(A10) + bias2[0], hsum2(A11) + bias2[1]);
            xg1[tt][1] = pk2(hsum2(A12) + bias2[2], hsum2(A13) + bias2[3]);
        }

        // ---- phase B: recurrence (w_hh2 in WR); h2 overwrites sy rows (dead y) ----
        #pragma unroll
        for (int g = 0; g < 4; ++g)
            #pragma unroll
            for (int qq = 0; qq < 8; ++qq) {
                ulonglong2 v = w2t[1024 + qq * 128 + g * 32 + lane];
                WR[g * 16 + 2 * qq]     = v.x;
                WR[g * 16 + 2 * qq + 1] = v.y;
            }
        #pragma unroll
        for (int tt = 0; tt < CH; ++tt) {
            float x00, x01, x02, x03, x10, x11, x12, x13;
            up2(xg0[tt][0], x00, x01);
            up2(xg0[tt][1], x02, x03);
            up2(xg1[tt][0], x10, x11);
            up2(xg1[tt][1], x12, x13);
            u64 A00 = pklo(x00), A01 = pklo(x01), A02 = pklo(x02), A03 = pklo(x03);
            u64 A10 = pklo(x10), A11 = pklo(x11), A12 = pklo(x12), A13 = pklo(x13);

            const ulonglong2* hp0 = (const ulonglong2*)(hb0 + buf * 32);
            const ulonglong2* hp1 = (const ulonglong2*)(hb1 + buf * 32);
            #pragma unroll
            for (int q = 0; q < 8; ++q) {
                const ulonglong2 hv0 = hp0[q];
                const ulonglong2 hv1 = hp1[q];
                A00 = ffma2(hv0.x, WR[2*q],      A00);  A10 = ffma2(hv1.x, WR[2*q],      A10);
                A00 = ffma2(hv0.y, WR[2*q+1],    A00);  A10 = ffma2(hv1.y, WR[2*q+1],    A10);
                A01 = ffma2(hv0.x, WR[16+2*q],   A01);  A11 = ffma2(hv1.x, WR[16+2*q],   A11);
                A01 = ffma2(hv0.y, WR[16+2*q+1], A01);  A11 = ffma2(hv1.y, WR[16+2*q+1], A11);
                A02 = ffma2(hv0.x, WR[32+2*q],   A02);  A12 = ffma2(hv1.x, WR[32+2*q],   A12);
                A02 = ffma2(hv0.y, WR[32+2*q+1], A02);  A12 = ffma2(hv1.y, WR[32+2*q+1], A12);
                A03 = ffma2(hv0.x, WR[48+2*q],   A03);  A13 = ffma2(hv1.x, WR[48+2*q],   A13);
                A03 = ffma2(hv0.y, WR[48+2*q+1], A03);  A13 = ffma2(hv1.y, WR[48+2*q+1], A13);
            }
            const float iv0 = sigm(hsum2(A00)), fv0 = sigm(hsum2(A01));
            const float gv0 = tanh_ap(hsum2(A02)), ov0 = sigm(hsum2(A03));
            const float iv1 = sigm(hsum2(A10)), fv1 = sigm(hsum2(A11));
            const float gv1 = tanh_ap(hsum2(A12)), ov1 = sigm(hsum2(A13));
            c0s = fv0 * c0s + iv0 * gv0;
            c1s = fv1 * c1s + iv1 * gv1;
            const float h20 = ov0 * tanh_ap(c0s);
            const float h21 = ov1 * tanh_ap(c1s);
            hb0[(buf ^ 1) * 32 + lane] = h20;
            hb1[(buf ^ 1) * 32 + lane] = h21;
            sy0[(t0 + tt) * HH + lane] = h20;   // dead y row -> h2 storage
            sy1[(t0 + tt) * HH + lane] = h21;
            __syncwarp();
            buf ^= 1;
        }
    }

    // ================= deferred output head =================
    // out[b,t] = <h2[t,:], w_out> + b_out ; lane L handles t = L and t = L+32.
    // Skewed index (k+lane)&31 keeps all smem reads conflict-free.
    const float bo = b_out[0];
    #pragma unroll 1
    for (int m = 0; m < SPW; ++m) {
        const float* sys = (m == 0) ? sy0 : sy1;
        float acc0 = 0.0f, acc1 = 0.0f;
        #pragma unroll
        for (int k = 0; k < HH; ++k) {
            const int idx = (k + lane) & 31;
            const float wv = swo[idx];
            acc0 = fmaf(sys[lane * HH + idx],        wv, acc0);
            acc1 = fmaf(sys[(lane + 32) * HH + idx], wv, acc1);
        }
        out[(size_t)(bbase + m) * SS + lane]      = acc0 + bo;
        out[(size_t)(bbase + m) * SS + lane + 32] = acc1 + bo;
    }
}

extern "C" void kernel_launch(void* const* d_in, const int* in_sizes, int n_in,
                              void* d_out, int out_size)
{
    const float* x_main = (const float*)d_in[0];
    const float* x_sfc  = (const float*)d_in[1];
    const float* w_sfc1 = (const float*)d_in[2];
    const float* b_sfc1 = (const float*)d_in[3];
    const float* w_sfc2 = (const float*)d_in[4];
    const float* b_sfc2 = (const float*)d_in[5];
    const float* w_ih1  = (const float*)d_in[6];
    const float* w_hh1  = (const float*)d_in[7];
    const float* b_ih1  = (const float*)d_in[8];
    const float* b_hh1  = (const float*)d_in[9];
    const float* w_ih2  = (const float*)d_in[10];
    const float* w_hh2  = (const float*)d_in[11];
    const float* b_ih2  = (const float*)d_in[12];
    const float* b_hh2  = (const float*)d_in[13];
    const float* w_out  = (const float*)d_in[14];
    const float* b_out  = (const float*)d_in[15];
    float* out = (float*)d_out;

    static bool attr_set = false;
    if (!attr_set) {
        cudaFuncSetAttribute(lstm_fused11, cudaFuncAttributeMaxDynamicSharedMemorySize, SMEM_BYTES);
        attr_set = true;
    }

    const int blocks = NB / BPB;   // 1024
    lstm_fused11<<<blocks, WPB * 32, SMEM_BYTES>>>(
        x_main, x_sfc, w_sfc1, b_sfc1, w_sfc2, b_sfc2,
        w_ih1, w_hh1, b_ih1, b_hh1,
        w_ih2, w_hh2, b_ih2, b_hh2,
        w_out, b_out, out);
}